// round 4
// baseline (speedup 1.0000x reference)
#include <cuda_runtime.h>
#include <cuda_bf16.h>
#include <cstdint>
#include <cstddef>

#define BATCH 4
#define SEQ   2048
#define DIM   1024
#define NQKV  3072
#define SCALE 0.03125f   // 1024^-0.5

typedef __nv_bfloat16 bf16;

// ---------------------------------------------------------------------------
// Scratch (static device globals — allocation-free per harness rules)
// ---------------------------------------------------------------------------
__device__ bf16  g_Xh[(size_t)BATCH * SEQ * DIM];
__device__ bf16  g_Xl[(size_t)BATCH * SEQ * DIM];
__device__ bf16  g_Wh[(size_t)NQKV * DIM];
__device__ bf16  g_Wl[(size_t)NQKV * DIM];
__device__ bf16  g_Qh[(size_t)BATCH * SEQ * DIM];   // pre-scaled by SCALE
__device__ bf16  g_Ql[(size_t)BATCH * SEQ * DIM];
__device__ bf16  g_Kh[(size_t)BATCH * SEQ * DIM];
__device__ bf16  g_Kl[(size_t)BATCH * SEQ * DIM];
__device__ float g_V [(size_t)BATCH * SEQ * DIM];   // row-major fp32 V
__device__ bf16  g_Vth[(size_t)BATCH * DIM * SEQ];  // [b, d, t]
__device__ bf16  g_Vtl[(size_t)BATCH * DIM * SEQ];
__device__ float g_S [(size_t)BATCH * SEQ * SEQ];   // scores fp32
__device__ bf16  g_Ph[(size_t)BATCH * SEQ * SEQ];   // softmax probs hi/lo
__device__ bf16  g_Pl[(size_t)BATCH * SEQ * SEQ];

// ---------------------------------------------------------------------------
// helpers
// ---------------------------------------------------------------------------
__device__ __forceinline__ uint32_t smem_u32(const void* p) {
    uint32_t a;
    asm("{ .reg .u64 t; cvta.to.shared.u64 t, %1; cvt.u32.u64 %0, t; }"
        : "=r"(a) : "l"(p));
    return a;
}

__device__ __forceinline__ void ldm4(uint32_t addr, uint32_t& r0, uint32_t& r1,
                                     uint32_t& r2, uint32_t& r3) {
    asm volatile("ldmatrix.sync.aligned.m8n8.x4.shared.b16 {%0,%1,%2,%3}, [%4];"
                 : "=r"(r0), "=r"(r1), "=r"(r2), "=r"(r3) : "r"(addr));
}

__device__ __forceinline__ void mma16816(float* d, const uint32_t* a, const uint32_t* b) {
    asm volatile(
        "mma.sync.aligned.m16n8k16.row.col.f32.bf16.bf16.f32 "
        "{%0,%1,%2,%3}, {%4,%5,%6,%7}, {%8,%9}, {%0,%1,%2,%3};"
        : "+f"(d[0]), "+f"(d[1]), "+f"(d[2]), "+f"(d[3])
        : "r"(a[0]), "r"(a[1]), "r"(a[2]), "r"(a[3]), "r"(b[0]), "r"(b[1]));
}

__device__ __forceinline__ void cp16(uint32_t dst, const void* src) {
    asm volatile("cp.async.cg.shared.global [%0], [%1], 16;" :: "r"(dst), "l"(src));
}
__device__ __forceinline__ void cp_commit() {
    asm volatile("cp.async.commit_group;" ::: "memory");
}
__device__ __forceinline__ void cp_wait1() {
    asm volatile("cp.async.wait_group 1;" ::: "memory");
}

// smem geometry: rows padded to 40 bf16 (80B) — conflict-free for ldmatrix
#define ROWB        80
#define MAT_BYTES   (128 * ROWB)                 // 10240 B (128 x 32 bf16 tile)
#define STAGE_BYTES (4 * MAT_BYTES)              // Ah | Al | Bh | Bl = 40960 B
#define SMEM_BYTES  (2 * STAGE_BYTES)            // 81920 B

// ---------------------------------------------------------------------------
// cp.async one stage: A/B tiles (128 rows x 32 k, hi & lo) for k-block kb.
// thread t: row = t>>1, chunks (t&1)*2 + {0,1} of 16B within the 64B payload.
// ---------------------------------------------------------------------------
__device__ __forceinline__ void issue_stage(const bf16* __restrict__ Ah,
                                            const bf16* __restrict__ Al,
                                            const bf16* __restrict__ Bh,
                                            const bf16* __restrict__ Bl,
                                            int K, int row0, int col0, int kb,
                                            uint32_t stg, int t) {
    const int r = t >> 1;
    const int c0 = (t & 1) * 2;
    const size_t aoff = (size_t)(row0 + r) * K + kb;
    const size_t boff = (size_t)(col0 + r) * K + kb;
    const uint32_t sr = stg + r * ROWB;
#pragma unroll
    for (int i = 0; i < 2; i++) {
        const int c = c0 + i;
        cp16(sr + c * 16,                 Ah + aoff + c * 8);
        cp16(sr + c * 16 + MAT_BYTES,     Al + aoff + c * 8);
        cp16(sr + c * 16 + 2 * MAT_BYTES, Bh + boff + c * 8);
        cp16(sr + c * 16 + 3 * MAT_BYTES, Bl + boff + c * 8);
    }
}

// ---------------------------------------------------------------------------
// bf16-split tensor-core GEMM: C[128,128] = A[M,K] * B[N,K]^T  (both K-major)
// MODE 0: X @ W^T  -> scatter to Qh/Ql(*SCALE), Kh/Kl, V(fp32 row-major)
// MODE 1: Q @ K^T  -> g_S      (per batch; scale pre-folded into Q)
// MODE 2: P @ Vt^T -> out      (per batch)
// ---------------------------------------------------------------------------
template <int MODE>
__global__ __launch_bounds__(256, 2) void mma_gemm(float* __restrict__ Out) {
    extern __shared__ char smem[];
    const uint32_t sm = smem_u32(smem);
    const int t = threadIdx.x;
    const int wid = t >> 5;
    const int l = t & 31;
    const int z = blockIdx.z;

    const bf16 *Ah, *Al, *Bh, *Bl;
    float* C = nullptr;
    int K;
    if (MODE == 0) {
        Ah = g_Xh; Al = g_Xl; Bh = g_Wh; Bl = g_Wl; K = DIM;
    } else if (MODE == 1) {
        Ah = g_Qh + (size_t)z * SEQ * DIM;  Al = g_Ql + (size_t)z * SEQ * DIM;
        Bh = g_Kh + (size_t)z * SEQ * DIM;  Bl = g_Kl + (size_t)z * SEQ * DIM;
        C = g_S + (size_t)z * SEQ * SEQ;    K = DIM;
    } else {
        Ah = g_Ph + (size_t)z * SEQ * SEQ;  Al = g_Pl + (size_t)z * SEQ * SEQ;
        Bh = g_Vth + (size_t)z * DIM * SEQ; Bl = g_Vtl + (size_t)z * DIM * SEQ;
        C = Out + (size_t)z * SEQ * DIM;    K = SEQ;
    }

    const int row0 = blockIdx.y * 128;
    const int col0 = blockIdx.x * 128;
    const int KI = K / 32;

    const int wm = (wid >> 2) * 64;     // warp M offset
    const int wn = (wid & 3) * 32;      // warp N offset

    const int a_row = l & 15;
    const int a_koff = ((l >> 4) & 1) * 8;
    const int b_row = (l & 7) + ((l >> 4) & 1) * 8;
    const int b_koff = ((l >> 3) & 1) * 8;

    float acc[4][4][4];
#pragma unroll
    for (int mi = 0; mi < 4; mi++)
#pragma unroll
        for (int ni = 0; ni < 4; ni++)
#pragma unroll
            for (int j = 0; j < 4; j++) acc[mi][ni][j] = 0.0f;

    // prologue: fill stage 0 and stage 1
    issue_stage(Ah, Al, Bh, Bl, K, row0, col0, 0, sm, t);
    cp_commit();
    issue_stage(Ah, Al, Bh, Bl, K, row0, col0, 32, sm + STAGE_BYTES, t);
    cp_commit();

    for (int it = 0; it < KI; it++) {
        const int s = it & 1;
        const uint32_t stg = sm + s * STAGE_BYTES;

        cp_wait1();            // stage s complete (<=1 group outstanding)
        __syncthreads();

        const uint32_t sAh = stg;
        const uint32_t sAl = stg + MAT_BYTES;
        const uint32_t sBh = stg + 2 * MAT_BYTES;
        const uint32_t sBl = stg + 3 * MAT_BYTES;
#pragma unroll
        for (int k0 = 0; k0 < 32; k0 += 16) {
            uint32_t bH[4][2], bL[4][2];
#pragma unroll
            for (int nb = 0; nb < 2; nb++) {
                const uint32_t off =
                    (uint32_t)((wn + nb * 16 + b_row) * ROWB + (k0 + b_koff) * 2);
                uint32_t r0, r1, r2, r3;
                ldm4(sBh + off, r0, r1, r2, r3);
                bH[2 * nb][0] = r0; bH[2 * nb][1] = r1;
                bH[2 * nb + 1][0] = r2; bH[2 * nb + 1][1] = r3;
                ldm4(sBl + off, r0, r1, r2, r3);
                bL[2 * nb][0] = r0; bL[2 * nb][1] = r1;
                bL[2 * nb + 1][0] = r2; bL[2 * nb + 1][1] = r3;
            }
#pragma unroll
            for (int mi = 0; mi < 4; mi++) {
                uint32_t aH[4], aL[4];
                const uint32_t off =
                    (uint32_t)((wm + mi * 16 + a_row) * ROWB + (k0 + a_koff) * 2);
                ldm4(sAh + off, aH[0], aH[1], aH[2], aH[3]);
                ldm4(sAl + off, aL[0], aL[1], aL[2], aL[3]);
#pragma unroll
                for (int ni = 0; ni < 4; ni++) {
                    mma16816(acc[mi][ni], aH, bH[ni]);
                    mma16816(acc[mi][ni], aH, bL[ni]);
                    mma16816(acc[mi][ni], aL, bH[ni]);
                }
            }
        }
        __syncthreads();       // all warps done reading stage s

        if (it + 2 < KI)
            issue_stage(Ah, Al, Bh, Bl, K, row0, col0, (it + 2) * 32, stg, t);
        cp_commit();           // keep group accounting uniform (may be empty)
    }

    // Epilogue: fragments -> padded smem -> gmem
    float* Csh = (float*)smem;                     // 128 x 130 fp32 (66.6 KB)
#pragma unroll
    for (int mi = 0; mi < 4; mi++)
#pragma unroll
        for (int ni = 0; ni < 4; ni++) {
            const int r = wm + mi * 16 + (l >> 2);
            const int c = wn + ni * 8 + (l & 3) * 2;
            Csh[r * 130 + c]           = acc[mi][ni][0];
            Csh[r * 130 + c + 1]       = acc[mi][ni][1];
            Csh[(r + 8) * 130 + c]     = acc[mi][ni][2];
            Csh[(r + 8) * 130 + c + 1] = acc[mi][ni][3];
        }
    __syncthreads();

    for (int i = t; i < 128 * 128; i += 256) {
        const int r = i >> 7, c = i & 127;
        const float v = Csh[r * 130 + c];
        if (MODE == 0) {
            const int grow = row0 + r;
            const int col = col0 + c;
            const int which = col % 3;             // qkv reshape (d,3)
            const int oc = col / 3;
            const size_t o = (size_t)grow * DIM + oc;
            if (which == 0) {
                const float q = v * SCALE;         // fold attention scale into Q
                const bf16 h = __float2bfloat16(q);
                g_Qh[o] = h;
                g_Ql[o] = __float2bfloat16(q - __bfloat162float(h));
            } else if (which == 1) {
                const bf16 h = __float2bfloat16(v);
                g_Kh[o] = h;
                g_Kl[o] = __float2bfloat16(v - __bfloat162float(h));
            } else {
                g_V[o] = v;
            }
        } else if (MODE == 1) {
            C[(size_t)(row0 + r) * SEQ + col0 + c] = v;
        } else {
            C[(size_t)(row0 + r) * DIM + col0 + c] = v;
        }
    }
}

// ---------------------------------------------------------------------------
// Elementwise fp32 -> bf16 hi/lo split (8 elements per thread)
// ---------------------------------------------------------------------------
__global__ __launch_bounds__(256) void cvt_k(const float* __restrict__ src,
                                             bf16* __restrict__ dh,
                                             bf16* __restrict__ dl, int n8) {
    const int i = blockIdx.x * 256 + threadIdx.x;
    if (i >= n8) return;
    const float4 a = *(const float4*)(src + (size_t)i * 8);
    const float4 b = *(const float4*)(src + (size_t)i * 8 + 4);
    float x[8] = {a.x, a.y, a.z, a.w, b.x, b.y, b.z, b.w};
    bf16 h[8], lo[8];
#pragma unroll
    for (int j = 0; j < 8; j++) {
        h[j] = __float2bfloat16(x[j]);
        lo[j] = __float2bfloat16(x[j] - __bfloat162float(h[j]));
    }
    *(uint4*)(dh + (size_t)i * 8) = *(const uint4*)h;
    *(uint4*)(dl + (size_t)i * 8) = *(const uint4*)lo;
}

// ---------------------------------------------------------------------------
// V [b, t, d] fp32 -> Vt hi/lo [b, d, t] bf16 (32x32 smem tiles)
// ---------------------------------------------------------------------------
__global__ __launch_bounds__(256) void vtrans_k() {
    __shared__ float s[32][33];
    const int tx = threadIdx.x & 31;
    const int ty = threadIdx.x >> 5;      // 0..7
    const int t0 = blockIdx.x * 32;
    const int d0 = blockIdx.y * 32;
    const int z = blockIdx.z;
    const float* V = g_V + (size_t)z * SEQ * DIM;
#pragma unroll
    for (int i = 0; i < 4; i++) {
        const int r = ty + i * 8;
        s[r][tx] = V[(size_t)(t0 + r) * DIM + d0 + tx];
    }
    __syncthreads();
    bf16* Oh = g_Vth + (size_t)z * DIM * SEQ;
    bf16* Ol = g_Vtl + (size_t)z * DIM * SEQ;
#pragma unroll
    for (int i = 0; i < 4; i++) {
        const int dr = ty + i * 8;
        const float v = s[tx][dr];
        const bf16 h = __float2bfloat16(v);
        const size_t o = (size_t)(d0 + dr) * SEQ + t0 + tx;
        Oh[o] = h;
        Ol[o] = __float2bfloat16(v - __bfloat162float(h));
    }
}

// ---------------------------------------------------------------------------
// Row softmax: g_S row (2048 fp32) -> P hi/lo bf16. 8 consecutive per thread.
// ---------------------------------------------------------------------------
__global__ __launch_bounds__(256) void softmax_k() {
    const size_t base = (size_t)blockIdx.x * SEQ;
    const float* p = g_S + base;
    const int t = threadIdx.x;
    const int lane = t & 31;
    const int warp = t >> 5;
    __shared__ float red[2][8];

    const float4 a = *(const float4*)(p + t * 8);
    const float4 b = *(const float4*)(p + t * 8 + 4);
    float v[8] = {a.x, a.y, a.z, a.w, b.x, b.y, b.z, b.w};

    float m = -1e30f;
#pragma unroll
    for (int i = 0; i < 8; i++) m = fmaxf(m, v[i]);
#pragma unroll
    for (int off = 16; off > 0; off >>= 1)
        m = fmaxf(m, __shfl_xor_sync(0xffffffffu, m, off));
    if (lane == 0) red[0][warp] = m;
    __syncthreads();
    m = red[0][0];
#pragma unroll
    for (int w = 1; w < 8; w++) m = fmaxf(m, red[0][w]);

    float s = 0.0f;
#pragma unroll
    for (int i = 0; i < 8; i++) { v[i] = __expf(v[i] - m); s += v[i]; }
#pragma unroll
    for (int off = 16; off > 0; off >>= 1)
        s += __shfl_xor_sync(0xffffffffu, s, off);
    if (lane == 0) red[1][warp] = s;
    __syncthreads();
    s = red[1][0];
#pragma unroll
    for (int w = 1; w < 8; w++) s += red[1][w];

    const float inv = 1.0f / s;
    bf16 h[8], lo[8];
#pragma unroll
    for (int i = 0; i < 8; i++) {
        const float q = v[i] * inv;
        h[i] = __float2bfloat16(q);
        lo[i] = __float2bfloat16(q - __bfloat162float(h[i]));
    }
    *(uint4*)(g_Ph + base + t * 8) = *(const uint4*)h;
    *(uint4*)(g_Pl + base + t * 8) = *(const uint4*)lo;
}

// ---------------------------------------------------------------------------
extern "C" void kernel_launch(void* const* d_in, const int* in_sizes, int n_in,
                              void* d_out, int out_size) {
    const float* x = (const float*)d_in[0];    // [4, 2048, 1024]
    const float* W = (const float*)d_in[1];    // [3072, 1024]
    float* out = (float*)d_out;                // [4, 2048, 1024]

    cudaFuncSetAttribute(mma_gemm<0>, cudaFuncAttributeMaxDynamicSharedMemorySize, SMEM_BYTES);
    cudaFuncSetAttribute(mma_gemm<1>, cudaFuncAttributeMaxDynamicSharedMemorySize, SMEM_BYTES);
    cudaFuncSetAttribute(mma_gemm<2>, cudaFuncAttributeMaxDynamicSharedMemorySize, SMEM_BYTES);

    // device-global symbol addresses (host side)
    bf16 *Xh, *Xl, *Wh, *Wl;
    cudaGetSymbolAddress((void**)&Xh, g_Xh);
    cudaGetSymbolAddress((void**)&Xl, g_Xl);
    cudaGetSymbolAddress((void**)&Wh, g_Wh);
    cudaGetSymbolAddress((void**)&Wl, g_Wl);

    // 0) split inputs to bf16 hi/lo
    cvt_k<<<(BATCH * SEQ * DIM / 8 + 255) / 256, 256>>>(x, Xh, Xl, BATCH * SEQ * DIM / 8);
    cvt_k<<<(NQKV * DIM / 8 + 255) / 256, 256>>>(W, Wh, Wl, NQKV * DIM / 8);

    // 1) QKV projection (epilogue emits Q/K hi-lo and fp32 V)
    mma_gemm<0><<<dim3(NQKV / 128, (BATCH * SEQ) / 128, 1), 256, SMEM_BYTES>>>(nullptr);

    // 2) V transpose + split
    vtrans_k<<<dim3(SEQ / 32, DIM / 32, BATCH), 256>>>();

    // 3) scores = (Q*scale) K^T
    mma_gemm<1><<<dim3(SEQ / 128, SEQ / 128, BATCH), 256, SMEM_BYTES>>>(nullptr);

    // 4) softmax -> P hi/lo
    softmax_k<<<dim3(BATCH * SEQ), 256>>>();

    // 5) out = P V
    mma_gemm<2><<<dim3(DIM / 128, SEQ / 128, BATCH), 256, SMEM_BYTES>>>(out);
}